// round 1
// baseline (speedup 1.0000x reference)
#include <cuda_runtime.h>

// BiGNNLayer: out = (features + x) @ W1 + b1 + (x * features) @ W2 + b2
// where x = segment_sum(lap_vals[:,None] * features[lap_cols], lap_rows)
//
// Inputs (metadata order):
//  0: lap_rows  int32 [E]
//  1: lap_cols  int32 [E]
//  2: lap_vals  f32   [E]
//  3: features  f32   [N, 64]
//  4: W1        f32   [64, 64]
//  5: b1        f32   [64]
//  6: W2        f32   [64, 64]
//  7: b2        f32   [64]
// Output: f32 [N, 64]

constexpr int DIM = 64;
constexpr int MAX_NODES = 100000;

// Scratch accumulator for x = L @ features. 25.6 MB, __device__ global (no alloc).
__device__ float4 g_x[MAX_NODES * (DIM / 4)];

// ---------------------------------------------------------------------------
// Kernel 1: zero the scratch accumulator
// ---------------------------------------------------------------------------
__global__ void zero_x_kernel(int n4) {
    int i = blockIdx.x * blockDim.x + threadIdx.x;
    if (i < n4) g_x[i] = make_float4(0.f, 0.f, 0.f, 0.f);
}

// ---------------------------------------------------------------------------
// Kernel 2: COO SpMM with vectorized reduction atomics.
// 16 threads per edge; each thread handles one float4 (4 of 64 dims).
// features table (25.6MB) is L2-resident; gathers mostly hit L2.
// red.global.add.v4.f32 (sm_90+) does 16B per atomic op -> 4x fewer issues.
// ---------------------------------------------------------------------------
__global__ void spmm_kernel(const int* __restrict__ rows,
                            const int* __restrict__ cols,
                            const float* __restrict__ vals,
                            const float4* __restrict__ feat,
                            int n_edges) {
    long long gid = (long long)blockIdx.x * blockDim.x + threadIdx.x;
    int e = (int)(gid >> 4);
    if (e >= n_edges) return;
    int c = (int)(gid & 15);

    int row  = __ldg(rows + e);
    int col  = __ldg(cols + e);
    float v  = __ldg(vals + e);

    float4 f = __ldg(feat + col * 16 + c);
    float mx = v * f.x, my = v * f.y, mz = v * f.z, mw = v * f.w;

    float* dst = reinterpret_cast<float*>(g_x + row * 16 + c);
    asm volatile("red.global.add.v4.f32 [%0], {%1, %2, %3, %4};"
                 :: "l"(dst), "f"(mx), "f"(my), "f"(mz), "f"(mw)
                 : "memory");
}

// ---------------------------------------------------------------------------
// Kernel 3: dense epilogue. Persistent blocks; weights live in shared memory.
// Block = 256 threads = 16 nodes x 16 output-column-groups (4 cols each).
// out[n][j] = sum_k (f[n][k]+x[n][k]) * W1[k][j] + (f[n][k]*x[n][k]) * W2[k][j]
//             + b1[j] + b2[j]
// ---------------------------------------------------------------------------
__global__ void dense_kernel(const float4* __restrict__ feat,
                             const float* __restrict__ W1,
                             const float* __restrict__ b1,
                             const float* __restrict__ W2,
                             const float* __restrict__ b2,
                             float4* __restrict__ out,
                             int n_nodes, int n_tiles) {
    __shared__ float W1s[DIM * DIM];   // 16 KB
    __shared__ float W2s[DIM * DIM];   // 16 KB
    __shared__ float bs[DIM];
    __shared__ float y1s[16 * DIM];    // 4 KB
    __shared__ float y2s[16 * DIM];    // 4 KB

    int tid = threadIdx.x;
    for (int i = tid; i < DIM * DIM; i += 256) {
        W1s[i] = W1[i];
        W2s[i] = W2[i];
    }
    if (tid < DIM) bs[tid] = b1[tid] + b2[tid];

    int nl = tid >> 4;       // local node   0..15
    int cg = tid & 15;       // column group 0..15 (float4 granularity)
    int j  = cg * 4;

    for (int tile = blockIdx.x; tile < n_tiles; tile += gridDim.x) {
        int node = tile * 16 + nl;

        __syncthreads();  // weights ready (1st iter); y buffers free (later iters)

        if (node < n_nodes) {
            float4 f = feat[node * 16 + cg];
            float4 x = g_x[node * 16 + cg];
            int base = nl * DIM + cg * 4;
            y1s[base + 0] = f.x + x.x;  y2s[base + 0] = f.x * x.x;
            y1s[base + 1] = f.y + x.y;  y2s[base + 1] = f.y * x.y;
            y1s[base + 2] = f.z + x.z;  y2s[base + 2] = f.z * x.z;
            y1s[base + 3] = f.w + x.w;  y2s[base + 3] = f.w * x.w;
        }
        __syncthreads();

        if (node < n_nodes) {
            float accx = bs[j + 0];
            float accy = bs[j + 1];
            float accz = bs[j + 2];
            float accw = bs[j + 3];
            #pragma unroll
            for (int k = 0; k < DIM; ++k) {
                float a1 = y1s[nl * DIM + k];
                float a2 = y2s[nl * DIM + k];
                float4 w1 = *reinterpret_cast<const float4*>(&W1s[k * DIM + j]);
                float4 w2 = *reinterpret_cast<const float4*>(&W2s[k * DIM + j]);
                accx += a1 * w1.x + a2 * w2.x;
                accy += a1 * w1.y + a2 * w2.y;
                accz += a1 * w1.z + a2 * w2.z;
                accw += a1 * w1.w + a2 * w2.w;
            }
            out[node * 16 + cg] = make_float4(accx, accy, accz, accw);
        }
    }
}

// ---------------------------------------------------------------------------
// Launch
// ---------------------------------------------------------------------------
extern "C" void kernel_launch(void* const* d_in, const int* in_sizes, int n_in,
                              void* d_out, int out_size) {
    const int*   rows = (const int*)d_in[0];
    const int*   cols = (const int*)d_in[1];
    const float* vals = (const float*)d_in[2];
    const float* feat = (const float*)d_in[3];
    const float* W1   = (const float*)d_in[4];
    const float* b1   = (const float*)d_in[5];
    const float* W2   = (const float*)d_in[6];
    const float* b2   = (const float*)d_in[7];

    int n_edges = in_sizes[0];
    int n_nodes = in_sizes[3] / DIM;

    // 1) zero scratch
    int n4 = n_nodes * (DIM / 4);
    zero_x_kernel<<<(n4 + 255) / 256, 256>>>(n4);

    // 2) SpMM: 16 threads per edge
    long long work = (long long)n_edges * 16;
    int blocks = (int)((work + 255) / 256);
    spmm_kernel<<<blocks, 256>>>(rows, cols, vals, (const float4*)feat, n_edges);

    // 3) dense epilogue (persistent grid)
    int n_tiles = (n_nodes + 15) / 16;
    int grid = n_tiles < 1184 ? n_tiles : 1184;
    dense_kernel<<<grid, 256>>>((const float4*)feat, W1, b1, W2, b2,
                                (float4*)d_out, n_nodes, n_tiles);
}

// round 2
// speedup vs baseline: 1.4325x; 1.4325x over previous
#include <cuda_runtime.h>

// BiGNNLayer: out = (features + x) @ W1 + b1 + (x * features) @ W2 + b2
// where x = segment_sum(lap_vals[:,None] * features[lap_cols], lap_rows)
//
// Strategy (R2): build CSR on device (counting sort) -> atomic-free gather SpMM
//                -> register-tiled dense epilogue.
//
// Inputs (metadata order):
//  0: lap_rows int32[E]  1: lap_cols int32[E]  2: lap_vals f32[E]
//  3: features f32[N,64] 4: W1 f32[64,64] 5: b1 f32[64] 6: W2 f32[64,64] 7: b2 f32[64]
// Output: f32 [N, 64]

constexpr int DIM = 64;
constexpr int MAX_NODES = 100000;
constexpr int MAX_EDGES = 3200000;
constexpr int SCAN_BLOCK = 1024;
constexpr int MAX_SCAN_BLOCKS = 128;   // supports N up to 131072

// Static device scratch (no runtime allocation allowed)
__device__ int    g_counts[MAX_NODES];
__device__ int    g_offsets[MAX_NODES];
__device__ int    g_cursor[MAX_NODES];
__device__ int    g_blocksums[MAX_SCAN_BLOCKS];
__device__ int2   g_sorted[MAX_EDGES];             // (col, val-as-int) row-sorted
__device__ float4 g_x[MAX_NODES * (DIM / 4)];      // x = L @ features

// ---------------------------------------------------------------------------
__global__ void zero_counts_kernel(int n) {
    int i = blockIdx.x * blockDim.x + threadIdx.x;
    if (i < n) g_counts[i] = 0;
}

__global__ void hist_kernel(const int* __restrict__ rows, int n_edges) {
    int e = blockIdx.x * blockDim.x + threadIdx.x;
    if (e < n_edges) atomicAdd(&g_counts[rows[e]], 1);
}

// Exclusive scan within 1024-blocks (Hillis-Steele), block totals out.
__global__ void scan_block_kernel(int n) {
    __shared__ int s[SCAN_BLOCK];
    int t = threadIdx.x;
    int idx = blockIdx.x * SCAN_BLOCK + t;
    int v = (idx < n) ? g_counts[idx] : 0;
    s[t] = v;
    __syncthreads();
    #pragma unroll
    for (int d = 1; d < SCAN_BLOCK; d <<= 1) {
        int tmp = (t >= d) ? s[t - d] : 0;
        __syncthreads();
        s[t] += tmp;
        __syncthreads();
    }
    if (idx < n) g_offsets[idx] = s[t] - v;              // exclusive
    if (t == SCAN_BLOCK - 1) g_blocksums[blockIdx.x] = s[t];  // block total
}

// Exclusive scan of block sums (single block).
__global__ void scan_sums_kernel(int nblk) {
    __shared__ int s[MAX_SCAN_BLOCKS];
    int t = threadIdx.x;
    int v = (t < nblk) ? g_blocksums[t] : 0;
    s[t] = v;
    __syncthreads();
    #pragma unroll
    for (int d = 1; d < MAX_SCAN_BLOCKS; d <<= 1) {
        int tmp = (t >= d) ? s[t - d] : 0;
        __syncthreads();
        s[t] += tmp;
        __syncthreads();
    }
    if (t < nblk) g_blocksums[t] = s[t] - v;
}

__global__ void add_offsets_kernel(int n) {
    int i = blockIdx.x * blockDim.x + threadIdx.x;
    if (i < n) {
        int o = g_offsets[i] + g_blocksums[i >> 10];
        g_offsets[i] = o;
        g_cursor[i] = o;
    }
}

__global__ void scatter_kernel(const int* __restrict__ rows,
                               const int* __restrict__ cols,
                               const float* __restrict__ vals,
                               int n_edges) {
    int e = blockIdx.x * blockDim.x + threadIdx.x;
    if (e >= n_edges) return;
    int r = rows[e];
    int pos = atomicAdd(&g_cursor[r], 1);
    g_sorted[pos] = make_int2(cols[e], __float_as_int(vals[e]));
}

// ---------------------------------------------------------------------------
// Gather SpMM: one warp per destination row. Lane owns dims {lane, lane+32}.
// Edge list read is warp-uniform (L1 broadcast); feature gather is 256B/warp
// per edge, fully coalesced, L2-resident (features table = 25.6MB).
// ---------------------------------------------------------------------------
__global__ void gather_kernel(const float* __restrict__ feat, int n_nodes) {
    int warp = (blockIdx.x * blockDim.x + threadIdx.x) >> 5;
    int lane = threadIdx.x & 31;
    if (warp >= n_nodes) return;

    int off = g_offsets[warp];
    int deg = g_counts[warp];

    float a0 = 0.f, a1 = 0.f;
    int i = 0;
    for (; i + 4 <= deg; i += 4) {
        int2 p0 = g_sorted[off + i + 0];
        int2 p1 = g_sorted[off + i + 1];
        int2 p2 = g_sorted[off + i + 2];
        int2 p3 = g_sorted[off + i + 3];
        const float* f0 = feat + (size_t)p0.x * DIM;
        const float* f1 = feat + (size_t)p1.x * DIM;
        const float* f2 = feat + (size_t)p2.x * DIM;
        const float* f3 = feat + (size_t)p3.x * DIM;
        // issue all 8 loads before the FMAs (MLP)
        float g00 = __ldg(f0 + lane), g01 = __ldg(f0 + lane + 32);
        float g10 = __ldg(f1 + lane), g11 = __ldg(f1 + lane + 32);
        float g20 = __ldg(f2 + lane), g21 = __ldg(f2 + lane + 32);
        float g30 = __ldg(f3 + lane), g31 = __ldg(f3 + lane + 32);
        float v0 = __int_as_float(p0.y), v1 = __int_as_float(p1.y);
        float v2 = __int_as_float(p2.y), v3 = __int_as_float(p3.y);
        a0 += v0 * g00; a1 += v0 * g01;
        a0 += v1 * g10; a1 += v1 * g11;
        a0 += v2 * g20; a1 += v2 * g21;
        a0 += v3 * g30; a1 += v3 * g31;
    }
    for (; i < deg; ++i) {
        int2 p = g_sorted[off + i];
        float v = __int_as_float(p.y);
        const float* f = feat + (size_t)p.x * DIM;
        a0 += v * __ldg(f + lane);
        a1 += v * __ldg(f + lane + 32);
    }

    float* xp = reinterpret_cast<float*>(g_x);
    xp[(size_t)warp * DIM + lane]      = a0;
    xp[(size_t)warp * DIM + lane + 32] = a1;
}

// ---------------------------------------------------------------------------
// Dense epilogue: block = 64-node tile x 64 cols, 256 threads.
// Thread computes 4 nodes x 4 cols. y tiles staged in padded smem;
// W read via __ldg (32KB, stays hot in L1; feat/x use streaming hint).
// ---------------------------------------------------------------------------
constexpr int YPAD = 68;  // 64 + 4, keeps float4 stores 16B-aligned, breaks conflicts

__global__ void dense_kernel(const float4* __restrict__ feat,
                             const float* __restrict__ W1,
                             const float* __restrict__ b1,
                             const float* __restrict__ W2,
                             const float* __restrict__ b2,
                             float4* __restrict__ out,
                             int n_nodes) {
    __shared__ float y1s[64 * YPAD];
    __shared__ float y2s[64 * YPAD];

    int t = threadIdx.x;
    int node0 = blockIdx.x * 64;

    // Stage y1 = f + x, y2 = f * x for 64 nodes (coalesced float4 loads).
    #pragma unroll
    for (int q = 0; q < 4; ++q) {
        int idx = q * 256 + t;           // 0..1023
        int nl = idx >> 4;               // local node 0..63
        int k4 = idx & 15;               // float4 chunk 0..15
        int node = node0 + nl;
        float4 f = make_float4(0.f, 0.f, 0.f, 0.f);
        float4 x = make_float4(0.f, 0.f, 0.f, 0.f);
        if (node < n_nodes) {
            f = __ldcs(feat + (size_t)node * 16 + k4);
            x = __ldcs(g_x + (size_t)node * 16 + k4);
        }
        float* p1 = &y1s[nl * YPAD + k4 * 4];
        float* p2 = &y2s[nl * YPAD + k4 * 4];
        p1[0] = f.x + x.x; p1[1] = f.y + x.y; p1[2] = f.z + x.z; p1[3] = f.w + x.w;
        p2[0] = f.x * x.x; p2[1] = f.y * x.y; p2[2] = f.z * x.z; p2[3] = f.w * x.w;
    }
    __syncthreads();

    int cg = t & 15;         // col group: j0 = cg*4
    int ng = t >> 4;         // node group: n0 = ng*4
    int j0 = cg * 4;
    int n0 = ng * 4;

    float acc[4][4];
    #pragma unroll
    for (int i = 0; i < 4; ++i)
        #pragma unroll
        for (int c = 0; c < 4; ++c) acc[i][c] = 0.f;

    #pragma unroll 8
    for (int k = 0; k < DIM; ++k) {
        float4 w1 = __ldg(reinterpret_cast<const float4*>(W1 + k * DIM + j0));
        float4 w2 = __ldg(reinterpret_cast<const float4*>(W2 + k * DIM + j0));
        #pragma unroll
        for (int i = 0; i < 4; ++i) {
            float a1 = y1s[(n0 + i) * YPAD + k];   // broadcast across 16 lanes
            float a2 = y2s[(n0 + i) * YPAD + k];
            acc[i][0] += a1 * w1.x + a2 * w2.x;
            acc[i][1] += a1 * w1.y + a2 * w2.y;
            acc[i][2] += a1 * w1.z + a2 * w2.z;
            acc[i][3] += a1 * w1.w + a2 * w2.w;
        }
    }

    float4 bb;
    bb.x = __ldg(b1 + j0 + 0) + __ldg(b2 + j0 + 0);
    bb.y = __ldg(b1 + j0 + 1) + __ldg(b2 + j0 + 1);
    bb.z = __ldg(b1 + j0 + 2) + __ldg(b2 + j0 + 2);
    bb.w = __ldg(b1 + j0 + 3) + __ldg(b2 + j0 + 3);

    #pragma unroll
    for (int i = 0; i < 4; ++i) {
        int node = node0 + n0 + i;
        if (node < n_nodes) {
            out[(size_t)node * 16 + cg] = make_float4(acc[i][0] + bb.x,
                                                      acc[i][1] + bb.y,
                                                      acc[i][2] + bb.z,
                                                      acc[i][3] + bb.w);
        }
    }
}

// ---------------------------------------------------------------------------
extern "C" void kernel_launch(void* const* d_in, const int* in_sizes, int n_in,
                              void* d_out, int out_size) {
    const int*   rows = (const int*)d_in[0];
    const int*   cols = (const int*)d_in[1];
    const float* vals = (const float*)d_in[2];
    const float* feat = (const float*)d_in[3];
    const float* W1   = (const float*)d_in[4];
    const float* b1   = (const float*)d_in[5];
    const float* W2   = (const float*)d_in[6];
    const float* b2   = (const float*)d_in[7];

    int n_edges = in_sizes[0];
    int n_nodes = in_sizes[3] / DIM;

    // 1) CSR build: histogram -> scan -> scatter
    zero_counts_kernel<<<(n_nodes + 255) / 256, 256>>>(n_nodes);
    hist_kernel<<<(n_edges + 255) / 256, 256>>>(rows, n_edges);

    int nblk = (n_nodes + SCAN_BLOCK - 1) / SCAN_BLOCK;
    scan_block_kernel<<<nblk, SCAN_BLOCK>>>(n_nodes);
    scan_sums_kernel<<<1, MAX_SCAN_BLOCKS>>>(nblk);
    add_offsets_kernel<<<(n_nodes + 255) / 256, 256>>>(n_nodes);

    scatter_kernel<<<(n_edges + 255) / 256, 256>>>(rows, cols, vals, n_edges);

    // 2) atomic-free gather SpMM: one warp per row
    long long threads = (long long)n_nodes * 32;
    gather_kernel<<<(int)((threads + 255) / 256), 256>>>(feat, n_nodes);

    // 3) dense epilogue
    dense_kernel<<<(n_nodes + 63) / 64, 256>>>((const float4*)feat, W1, b1,
                                               W2, b2, (float4*)d_out, n_nodes);
}